// round 10
// baseline (speedup 1.0000x reference)
#include <cuda_runtime.h>
#include <cuda_bf16.h>
#include <cstdint>

// ---------------------------------------------------------------------------
// Problem constants
// ---------------------------------------------------------------------------
#define BB 64
#define SS 8192
#define DD 128
#define UU 128
#define FF 16
#define CLIP_C 10.0f
#define BIG_NUMBER 1e9f
#define TS 64               // s-rows per CTA tile -> 2 CTAs/SM

// Scratch (device globals; no allocation allowed)
__device__ float          g_qb[BB * UU];        // q@W1 + b1 + b2
__device__ __nv_bfloat16  g_W2T_hi[UU * DD];    // W2^T hi split, [u][d]
__device__ __nv_bfloat16  g_W2T_lo[UU * DD];    // W2^T lo split, [u][d]

// ---------------------------------------------------------------------------
// Helpers (baseline PTX only: ldmatrix + mma.sync + approx MUFU)
// ---------------------------------------------------------------------------
__device__ __forceinline__ uint32_t smem_u32(const void* p) {
    uint32_t a;
    asm("{ .reg .u64 t; cvta.to.shared.u64 t, %1; cvt.u32.u64 %0, t; }"
        : "=r"(a) : "l"(p));
    return a;
}

#define LDMX4(r0, r1, r2, r3, addr) \
    asm volatile("ldmatrix.sync.aligned.m8n8.x4.shared.b16 {%0,%1,%2,%3}, [%4];" \
                 : "=r"(r0), "=r"(r1), "=r"(r2), "=r"(r3) : "r"(addr))

#define MMA16816(c0, c1, c2, c3, a0, a1, a2, a3, b0, b1) \
    asm volatile("mma.sync.aligned.m16n8k16.row.col.f32.bf16.bf16.f32 " \
                 "{%0,%1,%2,%3}, {%4,%5,%6,%7}, {%8,%9}, {%0,%1,%2,%3};" \
                 : "+f"(c0), "+f"(c1), "+f"(c2), "+f"(c3) \
                 : "r"(a0), "r"(a1), "r"(a2), "r"(a3), "r"(b0), "r"(b1))

// tanh(x) = 1 - 2/(exp(2x)+1), via ex2.approx + rcp.approx (~1e-6 abs err,
// monotonic -> ordering/argmax safe)
__device__ __forceinline__ float fast_tanh(float x) {
    float e, r;
    asm("ex2.approx.f32 %0, %1;" : "=f"(e) : "f"(x * 2.885390081777927f));
    asm("rcp.approx.f32 %0, %1;" : "=f"(r) : "f"(e + 1.0f));
    return fmaf(-2.0f, r, 1.0f);
}

__device__ __forceinline__ float fast_exp(float x) {
    float e;
    asm("ex2.approx.f32 %0, %1;" : "=f"(e) : "f"(x * 1.4426950408889634f));
    return e;
}

// ---------------------------------------------------------------------------
// Prep: qb (blocks 0..63) + W2^T bf16 hi/lo split (blocks 64..79)
// ---------------------------------------------------------------------------
__global__ void prep_kernel(const float* __restrict__ dec,
                            const float* __restrict__ W1w,
                            const float* __restrict__ W1b,
                            const float* __restrict__ W2b,
                            const float* __restrict__ W2w) {
    int blk = blockIdx.x;
    if (blk < BB) {
        int b = blk, u = threadIdx.x;
        __shared__ float dsh[DD];
        dsh[u] = dec[b * DD + u];
        __syncthreads();
        float acc = 0.f;
#pragma unroll 8
        for (int d = 0; d < DD; d++) acc += dsh[d] * W1w[d * UU + u];
        g_qb[b * UU + u] = acc + W1b[u] + W2b[u];
    } else {
        int j = blk - BB;           // 0..15 -> d rows j*8..j*8+7
        int u = threadIdx.x;        // 128 threads, coalesced W2w reads
#pragma unroll
        for (int k = 0; k < 8; k++) {
            int d = j * 8 + k;
            float x = W2w[d * UU + u];
            __nv_bfloat16 h = __float2bfloat16(x);
            float lo = x - __bfloat162float(h);
            g_W2T_hi[u * DD + d] = h;
            g_W2T_lo[u * DD + d] = __float2bfloat16(lo);
        }
    }
}

// ---------------------------------------------------------------------------
// Main kernel: per-CTA 64(s) x 128(u) tile, fused 3-term bf16-split mma.sync
// mainloop (fragments loaded once per kk, 24 MMAs back-to-back), fast-tanh
// epilogue. smem 106KB + <=128 regs -> 2 CTAs/SM for cross-CTA phase overlap.
// ---------------------------------------------------------------------------
#define ROWB 272u           // padded row stride in bytes (136 bf16)
#define SM_A_HI 0u
#define SM_A_LO (SM_A_HI + 64u * ROWB)       // 17408
#define SM_W_HI (SM_A_LO + 64u * ROWB)       // 34816
#define SM_W_LO (SM_W_HI + 128u * ROWB)      // 69632
#define SM_AUX  (SM_W_LO + 128u * ROWB)      // 104448
#define SM_Q    (SM_AUX)                      // 128 f32
#define SM_V    (SM_AUX + 512u)               // 128 f32
#define SM_PART (SM_AUX + 1024u)              // 64*2 f32
#define SM_TOTAL (SM_AUX + 1536u)

extern __shared__ unsigned char smx[];

__global__ void __launch_bounds__(256, 2)
main_kernel(const float* __restrict__ enc_out,
            const float* __restrict__ mask,
            const float* __restrict__ Vw,
            const float* __restrict__ Vb,
            float* __restrict__ logits) {
    const int b   = blockIdx.y;
    const int s0  = blockIdx.x * TS;
    const int tid = threadIdx.x;
    const int wid = tid >> 5;
    const int lid = tid & 31;
    const int m_tile = wid >> 1;   // 4 m-tiles of 16 s-rows
    const int n_half = wid & 1;    // 2 u-halves of 64
    const uint32_t sb = smem_u32(smx);

    float* sh_q    = (float*)(smx + SM_Q);
    float* sh_v    = (float*)(smx + SM_V);
    float* sh_part = (float*)(smx + SM_PART);

    if (tid < UU) { sh_q[tid] = g_qb[b * UU + tid]; sh_v[tid] = Vw[tid]; }

    // ---- fill A: 64 rows x 128 d, fp32 -> bf16 hi/lo, padded rows ----
    {
        const int row = tid >> 2;          // 0..63
        const int q   = tid & 3;           // d-quarter (32 floats)
        const float* src = enc_out + ((size_t)b * SS + s0 + row) * DD + q * 32;
        unsigned char* dhi = smx + SM_A_HI + row * ROWB + q * 64;
        unsigned char* dlo = smx + SM_A_LO + row * ROWB + q * 64;
#pragma unroll
        for (int i = 0; i < 8; i++) {
            float4 x = ((const float4*)src)[i];
            __nv_bfloat16 h0 = __float2bfloat16(x.x), h1 = __float2bfloat16(x.y);
            __nv_bfloat16 h2 = __float2bfloat16(x.z), h3 = __float2bfloat16(x.w);
            __nv_bfloat162 hp0 = __halves2bfloat162(h0, h1);
            __nv_bfloat162 hp1 = __halves2bfloat162(h2, h3);
            __nv_bfloat162 lp0 = __halves2bfloat162(
                __float2bfloat16(x.x - __bfloat162float(h0)),
                __float2bfloat16(x.y - __bfloat162float(h1)));
            __nv_bfloat162 lp1 = __halves2bfloat162(
                __float2bfloat16(x.z - __bfloat162float(h2)),
                __float2bfloat16(x.w - __bfloat162float(h3)));
            ((uint2*)dhi)[i] = make_uint2(*(uint32_t*)&hp0, *(uint32_t*)&hp1);
            ((uint2*)dlo)[i] = make_uint2(*(uint32_t*)&lp0, *(uint32_t*)&lp1);
        }
    }

    // ---- fill W: 128 u-rows x 128 d bf16 hi/lo, padded rows ----
    {
        const int row  = tid >> 1;
        const int half = tid & 1;
        const uint4* shi = (const uint4*)((const char*)g_W2T_hi + row * 256 + half * 128);
        const uint4* slo = (const uint4*)((const char*)g_W2T_lo + row * 256 + half * 128);
        uint4* dhi = (uint4*)(smx + SM_W_HI + row * ROWB + half * 128);
        uint4* dlo = (uint4*)(smx + SM_W_LO + row * ROWB + half * 128);
#pragma unroll
        for (int i = 0; i < 8; i++) { dhi[i] = shi[i]; dlo[i] = slo[i]; }
    }
    __syncthreads();

    // ---- per-lane ldmatrix base offsets ----
    const uint32_t a_off = (uint32_t)(m_tile * 16 + (lid & 15)) * ROWB
                         + (uint32_t)((lid >> 4) & 1) * 16u;
    const uint32_t b_off = (uint32_t)(n_half * 64 + (lid & 7) + ((lid >> 4) & 1) * 8) * ROWB
                         + (uint32_t)((lid >> 3) & 1) * 16u;

    const uint32_t a_hi_base = sb + SM_A_HI + a_off;
    const uint32_t a_lo_base = sb + SM_A_LO + a_off;
    const uint32_t w_hi_base = sb + SM_W_HI + b_off;
    const uint32_t w_lo_base = sb + SM_W_LO + b_off;

    float acc[8][4];
#pragma unroll
    for (int ni = 0; ni < 8; ni++)
#pragma unroll
        for (int j = 0; j < 4; j++) acc[ni][j] = 0.f;

    // ---- fused mainloop: fragments once per kk, 24 MMAs back-to-back ----
#pragma unroll 1
    for (int kk = 0; kk < 8; kk++) {
        const uint32_t kb = (uint32_t)kk * 32u;

        uint32_t ahi[4], alo[4];
        LDMX4(ahi[0], ahi[1], ahi[2], ahi[3], a_hi_base + kb);
        LDMX4(alo[0], alo[1], alo[2], alo[3], a_lo_base + kb);

        uint32_t whi[8][2], wlo[8][2];
#pragma unroll
        for (int np = 0; np < 4; np++) {
            LDMX4(whi[2 * np][0], whi[2 * np][1], whi[2 * np + 1][0], whi[2 * np + 1][1],
                  w_hi_base + (uint32_t)(np * 16) * ROWB + kb);
            LDMX4(wlo[2 * np][0], wlo[2 * np][1], wlo[2 * np + 1][0], wlo[2 * np + 1][1],
                  w_lo_base + (uint32_t)(np * 16) * ROWB + kb);
        }

#pragma unroll
        for (int ni = 0; ni < 8; ni++) {
            MMA16816(acc[ni][0], acc[ni][1], acc[ni][2], acc[ni][3],
                     ahi[0], ahi[1], ahi[2], ahi[3], whi[ni][0], whi[ni][1]);
            MMA16816(acc[ni][0], acc[ni][1], acc[ni][2], acc[ni][3],
                     ahi[0], ahi[1], ahi[2], ahi[3], wlo[ni][0], wlo[ni][1]);
            MMA16816(acc[ni][0], acc[ni][1], acc[ni][2], acc[ni][3],
                     alo[0], alo[1], alo[2], alo[3], whi[ni][0], whi[ni][1]);
        }
    }

    // ---- epilogue: sum_u V[u]*tanh(q[u]+K[s][u]) with fast tanh ----
    const int gid = lid >> 2;   // row within 8
    const int tig = lid & 3;    // col-pair selector
    float sum0 = 0.f, sum1 = 0.f;
#pragma unroll
    for (int ni = 0; ni < 8; ni++) {
        int cb = n_half * 64 + ni * 8 + 2 * tig;
        float v0 = sh_v[cb], v1 = sh_v[cb + 1];
        float q0 = sh_q[cb], q1 = sh_q[cb + 1];
        sum0 += v0 * fast_tanh(q0 + acc[ni][0]) + v1 * fast_tanh(q1 + acc[ni][1]);
        sum1 += v0 * fast_tanh(q0 + acc[ni][2]) + v1 * fast_tanh(q1 + acc[ni][3]);
    }
    sum0 += __shfl_xor_sync(0xffffffff, sum0, 1);
    sum0 += __shfl_xor_sync(0xffffffff, sum0, 2);
    sum1 += __shfl_xor_sync(0xffffffff, sum1, 1);
    sum1 += __shfl_xor_sync(0xffffffff, sum1, 2);
    if (tig == 0) {
        int r0 = m_tile * 16 + gid;
        sh_part[r0 * 2 + n_half] = sum0;
        sh_part[(r0 + 8) * 2 + n_half] = sum1;
    }
    __syncthreads();

    if (tid < TS) {
        float sc = sh_part[tid * 2] + sh_part[tid * 2 + 1] + Vb[0];
        float lg = CLIP_C * fast_tanh(sc)
                 - mask[(size_t)b * SS + s0 + tid] * BIG_NUMBER;
        logits[(size_t)b * SS + s0 + tid] = lg;
    }
}

// ---------------------------------------------------------------------------
// Softmax + first-occurrence argmax + gather (per batch), single-pass
// ---------------------------------------------------------------------------
#define SM_THREADS 512
#define PER_TH (SS / SM_THREADS)   // 16

__global__ void softmax_kernel(const float* __restrict__ logits,
                               const float* __restrict__ enc_input,
                               float* __restrict__ probs,
                               float* __restrict__ out_index,
                               float* __restrict__ gathered) {
    const int b = blockIdx.x;
    const int tid = threadIdx.x;
    const float* L = logits + (size_t)b * SS;
    float* P = probs + (size_t)b * SS;

    __shared__ float smax[SM_THREADS];
    __shared__ int   sidx[SM_THREADS];
    __shared__ float ssum[SM_THREADS];

    float vals[PER_TH];
    float bm = -3.0e38f; int bi = 0;
#pragma unroll
    for (int k = 0; k < PER_TH; k++) {
        int s = tid + k * SM_THREADS;
        float v = L[s];
        vals[k] = v;
        if (v > bm) { bm = v; bi = s; }
    }
    smax[tid] = bm; sidx[tid] = bi;
    __syncthreads();
    for (int off = SM_THREADS / 2; off > 0; off >>= 1) {
        if (tid < off) {
            float ov = smax[tid + off]; int oi = sidx[tid + off];
            if (ov > smax[tid] || (ov == smax[tid] && oi < sidx[tid])) {
                smax[tid] = ov; sidx[tid] = oi;
            }
        }
        __syncthreads();
    }
    const float M = smax[0];
    const int idx = sidx[0];

    float ls = 0.f;
#pragma unroll
    for (int k = 0; k < PER_TH; k++) {
        vals[k] = fast_exp(vals[k] - M);
        ls += vals[k];
    }
    ssum[tid] = ls;
    __syncthreads();
    for (int off = SM_THREADS / 2; off > 0; off >>= 1) {
        if (tid < off) ssum[tid] += ssum[tid + off];
        __syncthreads();
    }
    const float invZ = 1.0f / ssum[0];

#pragma unroll
    for (int k = 0; k < PER_TH; k++)
        P[tid + k * SM_THREADS] = vals[k] * invZ;

    if (tid == 0) out_index[b] = (float)idx;
    if (tid < FF)
        gathered[b * FF + tid] = enc_input[((size_t)b * SS + idx) * FF + tid];
}

// ---------------------------------------------------------------------------
// launch
// ---------------------------------------------------------------------------
extern "C" void kernel_launch(void* const* d_in, const int* in_sizes, int n_in,
                              void* d_out, int out_size) {
    const float* dec     = (const float*)d_in[0];
    const float* enc_in  = (const float*)d_in[1];
    const float* enc_out = (const float*)d_in[2];
    const float* mask    = (const float*)d_in[3];
    const float* W1w     = (const float*)d_in[4];
    const float* W1b     = (const float*)d_in[5];
    const float* W2w     = (const float*)d_in[6];
    const float* W2b     = (const float*)d_in[7];
    const float* Vw      = (const float*)d_in[8];
    const float* Vb      = (const float*)d_in[9];

    float* out    = (float*)d_out;
    float* logits = out;
    float* probs  = out + (size_t)BB * SS;
    float* oidx   = out + (size_t)2 * BB * SS;
    float* gath   = oidx + BB;

    cudaFuncSetAttribute(main_kernel,
                         cudaFuncAttributeMaxDynamicSharedMemorySize, SM_TOTAL);

    prep_kernel<<<BB + 16, 128>>>(dec, W1w, W1b, W2b, W2w);
    main_kernel<<<dim3(SS / TS, BB), 256, SM_TOTAL>>>(
        enc_out, mask, Vw, Vb, logits);
    softmax_kernel<<<BB, SM_THREADS>>>(logits, enc_in, probs, oidx, gath);
}

// round 12
// speedup vs baseline: 1.2565x; 1.2565x over previous
#include <cuda_runtime.h>
#include <cuda_bf16.h>
#include <cstdint>

// ---------------------------------------------------------------------------
// Problem constants
// ---------------------------------------------------------------------------
#define BB 64
#define SS 8192
#define DD 128
#define UU 128
#define FF 16
#define CLIP_C 10.0f
#define BIG_NUMBER 1e9f
#define TS 128
#define NTILES 4096          // (SS/TS) * BB
#define GRID_MAIN 152        // GB300 SM count

// Scratch (device globals; no allocation allowed)
__device__ float          g_qb[BB * UU];
__device__ __nv_bfloat16  g_W2T_hi[UU * DD];
__device__ __nv_bfloat16  g_W2T_lo[UU * DD];

// ---------------------------------------------------------------------------
// Helpers (baseline PTX only)
// ---------------------------------------------------------------------------
__device__ __forceinline__ uint32_t smem_u32(const void* p) {
    uint32_t a;
    asm("{ .reg .u64 t; cvta.to.shared.u64 t, %1; cvt.u32.u64 %0, t; }"
        : "=r"(a) : "l"(p));
    return a;
}

#define LDMX4(r0, r1, r2, r3, addr) \
    asm volatile("ldmatrix.sync.aligned.m8n8.x4.shared.b16 {%0,%1,%2,%3}, [%4];" \
                 : "=r"(r0), "=r"(r1), "=r"(r2), "=r"(r3) : "r"(addr))

#define MMA16816(c0, c1, c2, c3, a0, a1, a2, a3, b0, b1) \
    asm volatile("mma.sync.aligned.m16n8k16.row.col.f32.bf16.bf16.f32 " \
                 "{%0,%1,%2,%3}, {%4,%5,%6,%7}, {%8,%9}, {%0,%1,%2,%3};" \
                 : "+f"(c0), "+f"(c1), "+f"(c2), "+f"(c3) \
                 : "r"(a0), "r"(a1), "r"(a2), "r"(a3), "r"(b0), "r"(b1))

#define CP_ASYNC16(saddr, gptr) \
    asm volatile("cp.async.cg.shared.global [%0], [%1], 16;" \
                 :: "r"(saddr), "l"(gptr) : "memory")
#define CP_COMMIT() asm volatile("cp.async.commit_group;" ::: "memory")
#define CP_WAIT0()  asm volatile("cp.async.wait_group 0;" ::: "memory")

__device__ __forceinline__ float fast_tanh(float x) {
    float e, r;
    asm("ex2.approx.f32 %0, %1;" : "=f"(e) : "f"(x * 2.885390081777927f));
    asm("rcp.approx.f32 %0, %1;" : "=f"(r) : "f"(e + 1.0f));
    return fmaf(-2.0f, r, 1.0f);
}

__device__ __forceinline__ float fast_exp(float x) {
    float e;
    asm("ex2.approx.f32 %0, %1;" : "=f"(e) : "f"(x * 1.4426950408889634f));
    return e;
}

// ---------------------------------------------------------------------------
// Prep: qb (blocks 0..63, W1 cached in smem) + W2^T bf16 split (64..79)
// ---------------------------------------------------------------------------
extern __shared__ float prep_sm[];

__global__ void prep_kernel(const float* __restrict__ dec,
                            const float* __restrict__ W1w,
                            const float* __restrict__ W1b,
                            const float* __restrict__ W2b,
                            const float* __restrict__ W2w) {
    int blk = blockIdx.x;
    int tid = threadIdx.x;
    if (blk < BB) {
        __shared__ float dsh[DD];
        if (tid < DD) dsh[tid] = dec[blk * DD + tid];
        for (int i = tid; i < (DD * UU) / 4; i += 256)
            ((float4*)prep_sm)[i] = ((const float4*)W1w)[i];
        __syncthreads();
        if (tid < UU) {
            float acc = 0.f;
#pragma unroll 8
            for (int d = 0; d < DD; d++) acc += dsh[d] * prep_sm[d * UU + tid];
            g_qb[blk * UU + tid] = acc + W1b[tid] + W2b[tid];
        }
    } else if (tid < 128) {
        int j = blk - BB;           // 0..15 -> d rows j*8..j*8+7
        int u = tid;
#pragma unroll
        for (int k = 0; k < 8; k++) {
            int d = j * 8 + k;
            float x = W2w[d * UU + u];
            __nv_bfloat16 h = __float2bfloat16(x);
            float lo = x - __bfloat162float(h);
            g_W2T_hi[u * DD + d] = h;
            g_W2T_lo[u * DD + d] = __float2bfloat16(lo);
        }
    }
}

// ---------------------------------------------------------------------------
// Main: persistent CTAs, STATIC schedule t = bid + k*GRID (no atomics).
// W loaded/converted once per CTA. cp.async prefetch of next tile's fp32 A
// overlaps the fused 3-term bf16-split MMA loop + fast-tanh epilogue.
// ---------------------------------------------------------------------------
#define ROWB 272u
#define SM_W_HI  0u
#define SM_W_LO  (SM_W_HI + 128u * ROWB)     // 34816
#define SM_A_HI  (SM_W_LO + 128u * ROWB)     // 69632
#define SM_A_LO  (SM_A_HI + 128u * ROWB)     // 104448
#define SM_STAGE (SM_A_LO + 128u * ROWB)     // 139264, 64KB fp32
#define SM_AUX   (SM_STAGE + 65536u)         // 204800
#define SM_Q     (SM_AUX)
#define SM_V     (SM_AUX + 512u)
#define SM_PART  (SM_AUX + 1024u)            // 128*2 f32
#define SM_TOTAL (SM_AUX + 2048u)

extern __shared__ unsigned char smx[];

__global__ void __launch_bounds__(256, 1)
main_kernel(const float* __restrict__ enc_out,
            const float* __restrict__ mask,
            const float* __restrict__ Vw,
            const float* __restrict__ Vb,
            float* __restrict__ logits) {
    const int bid = blockIdx.x;
    const int tid = threadIdx.x;
    const int wid = tid >> 5;
    const int lid = tid & 31;
    const int warp_m = wid & 3;
    const int warp_n = wid >> 2;
    const uint32_t sb = smem_u32(smx);

    float* sh_q    = (float*)(smx + SM_Q);
    float* sh_v    = (float*)(smx + SM_V);
    float* sh_part = (float*)(smx + SM_PART);

    const float vb = Vb[0];
    if (tid < UU) sh_v[tid] = Vw[tid];

    // ---- W fill ONCE per CTA ----
    {
        const int row  = tid >> 1;
        const int half = tid & 1;
        const uint4* shi = (const uint4*)((const char*)g_W2T_hi + row * 256 + half * 128);
        const uint4* slo = (const uint4*)((const char*)g_W2T_lo + row * 256 + half * 128);
        uint4* dhi = (uint4*)(smx + SM_W_HI + row * ROWB + half * 128);
        uint4* dlo = (uint4*)(smx + SM_W_LO + row * ROWB + half * 128);
#pragma unroll
        for (int i = 0; i < 8; i++) { dhi[i] = shi[i]; dlo[i] = slo[i]; }
    }

    // ---- first prefetch ----
    int t = bid;
    if (t < NTILES) {
        const int b  = t >> 6;
        const int s0 = (t & 63) * TS;
        const char* src = (const char*)(enc_out + ((size_t)b * SS + s0) * DD);
#pragma unroll
        for (int i = 0; i < 16; i++) {
            uint32_t off = (uint32_t)(tid + 256 * i) * 16u;
            CP_ASYNC16(sb + SM_STAGE + off, src + off);
        }
        CP_COMMIT();
    }

    // ---- per-lane ldmatrix base offsets ----
    const uint32_t a_off = (uint32_t)(lid & 15) * ROWB + (uint32_t)((lid >> 4) & 1) * 16u
                           + (uint32_t)(warp_m * 32) * ROWB;
    const uint32_t b_off = ((uint32_t)(lid & 7) + (uint32_t)((lid >> 4) & 1) * 8u) * ROWB
                           + (uint32_t)((lid >> 3) & 1) * 16u
                           + (uint32_t)(warp_n * 64) * ROWB;
    const uint32_t a_hi_base = sb + SM_A_HI + a_off;
    const uint32_t a_lo_base = sb + SM_A_LO + a_off;
    const uint32_t w_hi_base = sb + SM_W_HI + b_off;
    const uint32_t w_lo_base = sb + SM_W_LO + b_off;

    while (t < NTILES) {
        const int b  = t >> 6;
        const int s0 = (t & 63) * TS;

        CP_WAIT0();
        __syncthreads();   // stage full; W ready (1st iter); prev epilogue done

        // ---- convert stage fp32 -> A bf16 hi/lo; load qb for this batch ----
        if (tid < UU) sh_q[tid] = g_qb[b * UU + tid];
        {
            const float4* stg = (const float4*)(smx + SM_STAGE);
#pragma unroll
            for (int i = 0; i < 16; i++) {
                int r = wid + 8 * i;
                float4 x = stg[(size_t)r * 32 + lid];
                __nv_bfloat16 h0 = __float2bfloat16(x.x), h1 = __float2bfloat16(x.y);
                __nv_bfloat16 h2 = __float2bfloat16(x.z), h3 = __float2bfloat16(x.w);
                __nv_bfloat162 hp0 = __halves2bfloat162(h0, h1);
                __nv_bfloat162 hp1 = __halves2bfloat162(h2, h3);
                __nv_bfloat162 lp0 = __halves2bfloat162(
                    __float2bfloat16(x.x - __bfloat162float(h0)),
                    __float2bfloat16(x.y - __bfloat162float(h1)));
                __nv_bfloat162 lp1 = __halves2bfloat162(
                    __float2bfloat16(x.z - __bfloat162float(h2)),
                    __float2bfloat16(x.w - __bfloat162float(h3)));
                *(uint2*)(smx + SM_A_HI + (uint32_t)r * ROWB + (uint32_t)lid * 8u) =
                    make_uint2(*(uint32_t*)&hp0, *(uint32_t*)&hp1);
                *(uint2*)(smx + SM_A_LO + (uint32_t)r * ROWB + (uint32_t)lid * 8u) =
                    make_uint2(*(uint32_t*)&lp0, *(uint32_t*)&lp1);
            }
        }
        __syncthreads();   // A ready; stage free

        // ---- prefetch next tile (overlaps MMA + epilogue below) ----
        const int tn = t + GRID_MAIN;
        if (tn < NTILES) {
            const int bn  = tn >> 6;
            const int sn0 = (tn & 63) * TS;
            const char* src = (const char*)(enc_out + ((size_t)bn * SS + sn0) * DD);
#pragma unroll
            for (int i = 0; i < 16; i++) {
                uint32_t off = (uint32_t)(tid + 256 * i) * 16u;
                CP_ASYNC16(sb + SM_STAGE + off, src + off);
            }
            CP_COMMIT();
        }

        // ---- fused 3-term MMA mainloop ----
        float acc[2][8][4];
#pragma unroll
        for (int mi = 0; mi < 2; mi++)
#pragma unroll
            for (int ni = 0; ni < 8; ni++)
#pragma unroll
                for (int j = 0; j < 4; j++) acc[mi][ni][j] = 0.f;

#pragma unroll 1
        for (int kk = 0; kk < 8; kk++) {
            const uint32_t kb = (uint32_t)kk * 32u;
            uint32_t ahi[2][4], alo[2][4];
            LDMX4(ahi[0][0], ahi[0][1], ahi[0][2], ahi[0][3], a_hi_base + kb);
            LDMX4(ahi[1][0], ahi[1][1], ahi[1][2], ahi[1][3], a_hi_base + 16u * ROWB + kb);
            LDMX4(alo[0][0], alo[0][1], alo[0][2], alo[0][3], a_lo_base + kb);
            LDMX4(alo[1][0], alo[1][1], alo[1][2], alo[1][3], a_lo_base + 16u * ROWB + kb);
            uint32_t whi[8][2], wlo[8][2];
#pragma unroll
            for (int np = 0; np < 4; np++) {
                LDMX4(whi[2 * np][0], whi[2 * np][1], whi[2 * np + 1][0], whi[2 * np + 1][1],
                      w_hi_base + (uint32_t)(np * 16) * ROWB + kb);
                LDMX4(wlo[2 * np][0], wlo[2 * np][1], wlo[2 * np + 1][0], wlo[2 * np + 1][1],
                      w_lo_base + (uint32_t)(np * 16) * ROWB + kb);
            }
#pragma unroll
            for (int mi = 0; mi < 2; mi++) {
#pragma unroll
                for (int ni = 0; ni < 8; ni++) {
                    MMA16816(acc[mi][ni][0], acc[mi][ni][1], acc[mi][ni][2], acc[mi][ni][3],
                             ahi[mi][0], ahi[mi][1], ahi[mi][2], ahi[mi][3],
                             whi[ni][0], whi[ni][1]);
                    MMA16816(acc[mi][ni][0], acc[mi][ni][1], acc[mi][ni][2], acc[mi][ni][3],
                             ahi[mi][0], ahi[mi][1], ahi[mi][2], ahi[mi][3],
                             wlo[ni][0], wlo[ni][1]);
                    MMA16816(acc[mi][ni][0], acc[mi][ni][1], acc[mi][ni][2], acc[mi][ni][3],
                             alo[mi][0], alo[mi][1], alo[mi][2], alo[mi][3],
                             whi[ni][0], whi[ni][1]);
                }
            }
        }

        // ---- epilogue ----
        const int gid = lid >> 2;
        const int tig = lid & 3;
#pragma unroll
        for (int mi = 0; mi < 2; mi++) {
            float sumA = 0.f, sumB = 0.f;
#pragma unroll
            for (int ni = 0; ni < 8; ni++) {
                int cb = warp_n * 64 + ni * 8 + 2 * tig;
                float v0 = sh_v[cb], v1 = sh_v[cb + 1];
                float q0 = sh_q[cb], q1 = sh_q[cb + 1];
                sumA += v0 * fast_tanh(q0 + acc[mi][ni][0]) + v1 * fast_tanh(q1 + acc[mi][ni][1]);
                sumB += v0 * fast_tanh(q0 + acc[mi][ni][2]) + v1 * fast_tanh(q1 + acc[mi][ni][3]);
            }
            sumA += __shfl_xor_sync(0xffffffff, sumA, 1);
            sumA += __shfl_xor_sync(0xffffffff, sumA, 2);
            sumB += __shfl_xor_sync(0xffffffff, sumB, 1);
            sumB += __shfl_xor_sync(0xffffffff, sumB, 2);
            if (tig == 0) {
                int rowA = warp_m * 32 + mi * 16 + gid;
                sh_part[rowA * 2 + warp_n] = sumA;
                sh_part[(rowA + 8) * 2 + warp_n] = sumB;
            }
        }
        __syncthreads();
        if (tid < TS) {
            float sc = sh_part[tid * 2] + sh_part[tid * 2 + 1] + vb;
            float lg = CLIP_C * fast_tanh(sc)
                     - mask[(size_t)b * SS + s0 + tid] * BIG_NUMBER;
            logits[(size_t)b * SS + s0 + tid] = lg;
        }

        t = tn;
    }
}

// ---------------------------------------------------------------------------
// Softmax + first-occurrence argmax + gather (per batch), single-pass
// ---------------------------------------------------------------------------
#define SM_THREADS 512
#define PER_TH (SS / SM_THREADS)   // 16

__global__ void softmax_kernel(const float* __restrict__ logits,
                               const float* __restrict__ enc_input,
                               float* __restrict__ probs,
                               float* __restrict__ out_index,
                               float* __restrict__ gathered) {
    const int b = blockIdx.x;
    const int tid = threadIdx.x;
    const float* L = logits + (size_t)b * SS;
    float* P = probs + (size_t)b * SS;

    __shared__ float smax[SM_THREADS];
    __shared__ int   sidx[SM_THREADS];
    __shared__ float ssum[SM_THREADS];

    float vals[PER_TH];
    float bm = -3.0e38f; int bi = 0;
#pragma unroll
    for (int k = 0; k < PER_TH; k++) {
        int s = tid + k * SM_THREADS;
        float v = L[s];
        vals[k] = v;
        if (v > bm) { bm = v; bi = s; }
    }
    smax[tid] = bm; sidx[tid] = bi;
    __syncthreads();
    for (int off = SM_THREADS / 2; off > 0; off >>= 1) {
        if (tid < off) {
            float ov = smax[tid + off]; int oi = sidx[tid + off];
            if (ov > smax[tid] || (ov == smax[tid] && oi < sidx[tid])) {
                smax[tid] = ov; sidx[tid] = oi;
            }
        }
        __syncthreads();
    }
    const float M = smax[0];
    const int idx = sidx[0];

    float ls = 0.f;
#pragma unroll
    for (int k = 0; k < PER_TH; k++) {
        vals[k] = fast_exp(vals[k] - M);
        ls += vals[k];
    }
    ssum[tid] = ls;
    __syncthreads();
    for (int off = SM_THREADS / 2; off > 0; off >>= 1) {
        if (tid < off) ssum[tid] += ssum[tid + off];
        __syncthreads();
    }
    const float invZ = 1.0f / ssum[0];

#pragma unroll
    for (int k = 0; k < PER_TH; k++)
        P[tid + k * SM_THREADS] = vals[k] * invZ;

    if (tid == 0) out_index[b] = (float)idx;
    if (tid < FF)
        gathered[b * FF + tid] = enc_input[((size_t)b * SS + idx) * FF + tid];
}

// ---------------------------------------------------------------------------
// launch
// ---------------------------------------------------------------------------
extern "C" void kernel_launch(void* const* d_in, const int* in_sizes, int n_in,
                              void* d_out, int out_size) {
    const float* dec     = (const float*)d_in[0];
    const float* enc_in  = (const float*)d_in[1];
    const float* enc_out = (const float*)d_in[2];
    const float* mask    = (const float*)d_in[3];
    const float* W1w     = (const float*)d_in[4];
    const float* W1b     = (const float*)d_in[5];
    const float* W2w     = (const float*)d_in[6];
    const float* W2b     = (const float*)d_in[7];
    const float* Vw      = (const float*)d_in[8];
    const float* Vb      = (const float*)d_in[9];

    float* out    = (float*)d_out;
    float* logits = out;
    float* probs  = out + (size_t)BB * SS;
    float* oidx   = out + (size_t)2 * BB * SS;
    float* gath   = oidx + BB;

    cudaFuncSetAttribute(prep_kernel,
                         cudaFuncAttributeMaxDynamicSharedMemorySize, DD * UU * 4);
    cudaFuncSetAttribute(main_kernel,
                         cudaFuncAttributeMaxDynamicSharedMemorySize, SM_TOTAL);

    prep_kernel<<<BB + 16, 256, DD * UU * 4>>>(dec, W1w, W1b, W2b, W2w);
    main_kernel<<<GRID_MAIN, 256, SM_TOTAL>>>(enc_out, mask, Vw, Vb, logits);
    softmax_kernel<<<BB, SM_THREADS>>>(logits, enc_in, probs, oidx, gath);
}

// round 14
// speedup vs baseline: 1.6151x; 1.2854x over previous
#include <cuda_runtime.h>
#include <cuda_bf16.h>
#include <cstdint>

// ---------------------------------------------------------------------------
// Problem constants
// ---------------------------------------------------------------------------
#define BB 64
#define SS 8192
#define DD 128
#define UU 128
#define FF 16
#define CLIP_C 10.0f
#define BIG_NUMBER 1e9f
#define TS 128
#define NTILES 4096          // (SS/TS) * BB
#define GRID_MAIN 152        // GB300 SM count

// Scratch (device globals; no allocation allowed)
__device__ float          g_qb[BB * UU];
__device__ __nv_bfloat16  g_W2T_hi[UU * DD];
__device__ __nv_bfloat16  g_W2T_lo[UU * DD];

// ---------------------------------------------------------------------------
// Helpers (baseline PTX only)
// ---------------------------------------------------------------------------
__device__ __forceinline__ uint32_t smem_u32(const void* p) {
    uint32_t a;
    asm("{ .reg .u64 t; cvta.to.shared.u64 t, %1; cvt.u32.u64 %0, t; }"
        : "=r"(a) : "l"(p));
    return a;
}

#define LDMX4(r0, r1, r2, r3, addr) \
    asm volatile("ldmatrix.sync.aligned.m8n8.x4.shared.b16 {%0,%1,%2,%3}, [%4];" \
                 : "=r"(r0), "=r"(r1), "=r"(r2), "=r"(r3) : "r"(addr))

#define MMA16816(c0, c1, c2, c3, a0, a1, a2, a3, b0, b1) \
    asm volatile("mma.sync.aligned.m16n8k16.row.col.f32.bf16.bf16.f32 " \
                 "{%0,%1,%2,%3}, {%4,%5,%6,%7}, {%8,%9}, {%0,%1,%2,%3};" \
                 : "+f"(c0), "+f"(c1), "+f"(c2), "+f"(c3) \
                 : "r"(a0), "r"(a1), "r"(a2), "r"(a3), "r"(b0), "r"(b1))

__device__ __forceinline__ float fast_tanh(float x) {
    float e, r;
    asm("ex2.approx.f32 %0, %1;" : "=f"(e) : "f"(x * 2.885390081777927f));
    asm("rcp.approx.f32 %0, %1;" : "=f"(r) : "f"(e + 1.0f));
    return fmaf(-2.0f, r, 1.0f);
}

__device__ __forceinline__ float fast_exp(float x) {
    float e;
    asm("ex2.approx.f32 %0, %1;" : "=f"(e) : "f"(x * 1.4426950408889634f));
    return e;
}

// convert one fp32 float4 -> bf16 hi/lo packed pairs, store to A buffers
__device__ __forceinline__ void cvt_store(unsigned char* base_hi,
                                          unsigned char* base_lo,
                                          uint32_t off, float4 x) {
    __nv_bfloat16 h0 = __float2bfloat16(x.x), h1 = __float2bfloat16(x.y);
    __nv_bfloat16 h2 = __float2bfloat16(x.z), h3 = __float2bfloat16(x.w);
    __nv_bfloat162 hp0 = __halves2bfloat162(h0, h1);
    __nv_bfloat162 hp1 = __halves2bfloat162(h2, h3);
    __nv_bfloat162 lp0 = __halves2bfloat162(
        __float2bfloat16(x.x - __bfloat162float(h0)),
        __float2bfloat16(x.y - __bfloat162float(h1)));
    __nv_bfloat162 lp1 = __halves2bfloat162(
        __float2bfloat16(x.z - __bfloat162float(h2)),
        __float2bfloat16(x.w - __bfloat162float(h3)));
    *(uint2*)(base_hi + off) = make_uint2(*(uint32_t*)&hp0, *(uint32_t*)&hp1);
    *(uint2*)(base_lo + off) = make_uint2(*(uint32_t*)&lp0, *(uint32_t*)&lp1);
}

// ---------------------------------------------------------------------------
// Prep: qb (blocks 0..63, W1 cached in smem) + W2^T bf16 split (64..79)
// ---------------------------------------------------------------------------
extern __shared__ float prep_sm[];

__global__ void prep_kernel(const float* __restrict__ dec,
                            const float* __restrict__ W1w,
                            const float* __restrict__ W1b,
                            const float* __restrict__ W2b,
                            const float* __restrict__ W2w) {
    int blk = blockIdx.x;
    int tid = threadIdx.x;
    if (blk < BB) {
        __shared__ float dsh[DD];
        if (tid < DD) dsh[tid] = dec[blk * DD + tid];
        for (int i = tid; i < (DD * UU) / 4; i += 256)
            ((float4*)prep_sm)[i] = ((const float4*)W1w)[i];
        __syncthreads();
        if (tid < UU) {
            float acc = 0.f;
#pragma unroll 8
            for (int d = 0; d < DD; d++) acc += dsh[d] * prep_sm[d * UU + tid];
            g_qb[blk * UU + tid] = acc + W1b[tid] + W2b[tid];
        }
    } else if (tid < 128) {
        int j = blk - BB;
        int u = tid;
#pragma unroll
        for (int k = 0; k < 8; k++) {
            int d = j * 8 + k;
            float x = W2w[d * UU + u];
            __nv_bfloat16 h = __float2bfloat16(x);
            float lo = x - __bfloat162float(h);
            g_W2T_hi[u * DD + d] = h;
            g_W2T_lo[u * DD + d] = __float2bfloat16(lo);
        }
    }
}

// ---------------------------------------------------------------------------
// Main: persistent CTAs, static schedule. W once per CTA. Double-buffered A:
// next tile's LDG + fp32->bf16 convert is interleaved INTO the MMA kk-loop
// (tensor pipe shadows LSU/FMA work). No fp32 stage, no cp.async.
// ---------------------------------------------------------------------------
#define ROWB 272u
#define SM_W_HI  0u
#define SM_W_LO  (SM_W_HI + 128u * ROWB)     // 34816
#define SM_A0    (SM_W_LO + 128u * ROWB)     // 69632  (hi at +0, lo at +34816)
#define SM_A1    (SM_A0 + 2u * 128u * ROWB)  // 139264
#define SM_AUX   (SM_A1 + 2u * 128u * ROWB)  // 208896
#define SM_Q0    (SM_AUX)                    // 128 f32
#define SM_Q1    (SM_AUX + 512u)             // 128 f32
#define SM_V     (SM_AUX + 1024u)            // 128 f32
#define SM_PART  (SM_AUX + 1536u)            // 128*2 f32
#define SM_TOTAL (SM_AUX + 2560u)            // 211456

extern __shared__ unsigned char smx[];

__global__ void __launch_bounds__(256, 1)
main_kernel(const float* __restrict__ enc_out,
            const float* __restrict__ mask,
            const float* __restrict__ Vw,
            const float* __restrict__ Vb,
            float* __restrict__ logits) {
    const int bid = blockIdx.x;
    const int tid = threadIdx.x;
    const int wid = tid >> 5;
    const int lid = tid & 31;
    const int warp_m = wid & 3;
    const int warp_n = wid >> 2;
    const uint32_t sb = smem_u32(smx);

    float* sh_v    = (float*)(smx + SM_V);
    float* sh_part = (float*)(smx + SM_PART);

    const float vb = Vb[0];
    if (tid < UU) sh_v[tid] = Vw[tid];

    // ---- W fill ONCE per CTA ----
    {
        const int row  = tid >> 1;
        const int half = tid & 1;
        const uint4* shi = (const uint4*)((const char*)g_W2T_hi + row * 256 + half * 128);
        const uint4* slo = (const uint4*)((const char*)g_W2T_lo + row * 256 + half * 128);
        uint4* dhi = (uint4*)(smx + SM_W_HI + row * ROWB + half * 128);
        uint4* dlo = (uint4*)(smx + SM_W_LO + row * ROWB + half * 128);
#pragma unroll
        for (int i = 0; i < 8; i++) { dhi[i] = shi[i]; dlo[i] = slo[i]; }
    }

    // ---- initial convert of tile t into A0 (latency exposed once) ----
    int t = bid;
    if (t < NTILES) {
        const int b  = t >> 6;
        const int s0 = (t & 63) * TS;
        const float* src = enc_out + ((size_t)b * SS + s0) * DD;
        unsigned char* bhi = smx + SM_A0;
        unsigned char* blo = smx + SM_A0 + 34816u;
#pragma unroll
        for (int i = 0; i < 16; i++) {
            int r = wid + 8 * i;
            float4 x = *(const float4*)(src + (size_t)r * DD + lid * 4);
            cvt_store(bhi, blo, (uint32_t)r * ROWB + (uint32_t)lid * 8u, x);
        }
        if (tid < UU) ((float*)(smx + SM_Q0))[tid] = g_qb[b * UU + tid];
    }
    __syncthreads();

    // ---- per-lane ldmatrix base offsets (relative) ----
    const uint32_t a_off = (uint32_t)(lid & 15) * ROWB + (uint32_t)((lid >> 4) & 1) * 16u
                           + (uint32_t)(warp_m * 32) * ROWB;
    const uint32_t b_off = ((uint32_t)(lid & 7) + (uint32_t)((lid >> 4) & 1) * 8u) * ROWB
                           + (uint32_t)((lid >> 3) & 1) * 16u
                           + (uint32_t)(warp_n * 64) * ROWB;
    const uint32_t w_hi_base = sb + SM_W_HI + b_off;
    const uint32_t w_lo_base = sb + SM_W_LO + b_off;

    int cur = 0;
    while (t < NTILES) {
        const int b  = t >> 6;
        const int s0 = (t & 63) * TS;
        const int tn = t + GRID_MAIN;
        const bool pf = tn < NTILES;

        const uint32_t a_cur = cur ? SM_A1 : SM_A0;
        const uint32_t a_alt = cur ? SM_A0 : SM_A1;
        const uint32_t a_hi_base = sb + a_cur + a_off;
        const uint32_t a_lo_base = sb + a_cur + 34816u + a_off;
        unsigned char* alt_hi = smx + a_alt;
        unsigned char* alt_lo = smx + a_alt + 34816u;
        float* sh_q  = (float*)(smx + (cur ? SM_Q1 : SM_Q0));
        float* sh_qn = (float*)(smx + (cur ? SM_Q0 : SM_Q1));

        const float* nsrc = nullptr;
        int bn = 0;
        if (pf) {
            bn = tn >> 6;
            const int sn0 = (tn & 63) * TS;
            nsrc = enc_out + ((size_t)bn * SS + sn0) * DD;
            if (tid < UU) sh_qn[tid] = g_qb[bn * UU + tid];
        }

        // ---- fused 3-term MMA mainloop + interleaved next-tile convert ----
        float acc[2][8][4];
#pragma unroll
        for (int mi = 0; mi < 2; mi++)
#pragma unroll
            for (int ni = 0; ni < 8; ni++)
#pragma unroll
                for (int j = 0; j < 4; j++) acc[mi][ni][j] = 0.f;

#pragma unroll 1
        for (int kk = 0; kk < 8; kk++) {
            const uint32_t kb = (uint32_t)kk * 32u;

            // issue next-tile LDGs early (latency hidden under this kk's MMAs)
            float4 nx0, nx1;
            int r0 = wid + 8 * (2 * kk);
            int r1 = wid + 8 * (2 * kk + 1);
            if (pf) {
                nx0 = *(const float4*)(nsrc + (size_t)r0 * DD + lid * 4);
                nx1 = *(const float4*)(nsrc + (size_t)r1 * DD + lid * 4);
            }

            uint32_t ahi[2][4], alo[2][4];
            LDMX4(ahi[0][0], ahi[0][1], ahi[0][2], ahi[0][3], a_hi_base + kb);
            LDMX4(ahi[1][0], ahi[1][1], ahi[1][2], ahi[1][3], a_hi_base + 16u * ROWB + kb);
            LDMX4(alo[0][0], alo[0][1], alo[0][2], alo[0][3], a_lo_base + kb);
            LDMX4(alo[1][0], alo[1][1], alo[1][2], alo[1][3], a_lo_base + 16u * ROWB + kb);
            uint32_t whi[8][2], wlo[8][2];
#pragma unroll
            for (int np = 0; np < 4; np++) {
                LDMX4(whi[2 * np][0], whi[2 * np][1], whi[2 * np + 1][0], whi[2 * np + 1][1],
                      w_hi_base + (uint32_t)(np * 16) * ROWB + kb);
                LDMX4(wlo[2 * np][0], wlo[2 * np][1], wlo[2 * np + 1][0], wlo[2 * np + 1][1],
                      w_lo_base + (uint32_t)(np * 16) * ROWB + kb);
            }
#pragma unroll
            for (int mi = 0; mi < 2; mi++) {
#pragma unroll
                for (int ni = 0; ni < 8; ni++) {
                    MMA16816(acc[mi][ni][0], acc[mi][ni][1], acc[mi][ni][2], acc[mi][ni][3],
                             ahi[mi][0], ahi[mi][1], ahi[mi][2], ahi[mi][3],
                             whi[ni][0], whi[ni][1]);
                    MMA16816(acc[mi][ni][0], acc[mi][ni][1], acc[mi][ni][2], acc[mi][ni][3],
                             ahi[mi][0], ahi[mi][1], ahi[mi][2], ahi[mi][3],
                             wlo[ni][0], wlo[ni][1]);
                    MMA16816(acc[mi][ni][0], acc[mi][ni][1], acc[mi][ni][2], acc[mi][ni][3],
                             alo[mi][0], alo[mi][1], alo[mi][2], alo[mi][3],
                             whi[ni][0], whi[ni][1]);
                }
            }

            // convert + store next-tile rows (FMA/LSU work under tensor shadow)
            if (pf) {
                cvt_store(alt_hi, alt_lo, (uint32_t)r0 * ROWB + (uint32_t)lid * 8u, nx0);
                cvt_store(alt_hi, alt_lo, (uint32_t)r1 * ROWB + (uint32_t)lid * 8u, nx1);
            }
        }

        __syncthreads();   // A[alt] complete; sh_part free for this iteration

        // ---- epilogue ----
        const int gid = lid >> 2;
        const int tig = lid & 3;
#pragma unroll
        for (int mi = 0; mi < 2; mi++) {
            float sumA = 0.f, sumB = 0.f;
#pragma unroll
            for (int ni = 0; ni < 8; ni++) {
                int cb = warp_n * 64 + ni * 8 + 2 * tig;
                float v0 = sh_v[cb], v1 = sh_v[cb + 1];
                float q0 = sh_q[cb], q1 = sh_q[cb + 1];
                sumA += v0 * fast_tanh(q0 + acc[mi][ni][0]) + v1 * fast_tanh(q1 + acc[mi][ni][1]);
                sumB += v0 * fast_tanh(q0 + acc[mi][ni][2]) + v1 * fast_tanh(q1 + acc[mi][ni][3]);
            }
            sumA += __shfl_xor_sync(0xffffffff, sumA, 1);
            sumA += __shfl_xor_sync(0xffffffff, sumA, 2);
            sumB += __shfl_xor_sync(0xffffffff, sumB, 1);
            sumB += __shfl_xor_sync(0xffffffff, sumB, 2);
            if (tig == 0) {
                int rowA = warp_m * 32 + mi * 16 + gid;
                sh_part[rowA * 2 + warp_n] = sumA;
                sh_part[(rowA + 8) * 2 + warp_n] = sumB;
            }
        }
        __syncthreads();
        if (tid < TS) {
            float sc = sh_part[tid * 2] + sh_part[tid * 2 + 1] + vb;
            float lg = CLIP_C * fast_tanh(sc)
                     - mask[(size_t)b * SS + s0 + tid] * BIG_NUMBER;
            logits[(size_t)b * SS + s0 + tid] = lg;
        }

        t = tn;
        cur ^= 1;
    }
}

// ---------------------------------------------------------------------------
// Softmax + first-occurrence argmax + gather (per batch), single-pass
// ---------------------------------------------------------------------------
#define SM_THREADS 512
#define PER_TH (SS / SM_THREADS)   // 16

__global__ void softmax_kernel(const float* __restrict__ logits,
                               const float* __restrict__ enc_input,
                               float* __restrict__ probs,
                               float* __restrict__ out_index,
                               float* __restrict__ gathered) {
    const int b = blockIdx.x;
    const int tid = threadIdx.x;
    const float* L = logits + (size_t)b * SS;
    float* P = probs + (size_t)b * SS;

    __shared__ float smax[SM_THREADS];
    __shared__ int   sidx[SM_THREADS];
    __shared__ float ssum[SM_THREADS];

    float vals[PER_TH];
    float bm = -3.0e38f; int bi = 0;
#pragma unroll
    for (int k = 0; k < PER_TH; k++) {
        int s = tid + k * SM_THREADS;
        float v = L[s];
        vals[k] = v;
        if (v > bm) { bm = v; bi = s; }
    }
    smax[tid] = bm; sidx[tid] = bi;
    __syncthreads();
    for (int off = SM_THREADS / 2; off > 0; off >>= 1) {
        if (tid < off) {
            float ov = smax[tid + off]; int oi = sidx[tid + off];
            if (ov > smax[tid] || (ov == smax[tid] && oi < sidx[tid])) {
                smax[tid] = ov; sidx[tid] = oi;
            }
        }
        __syncthreads();
    }
    const float M = smax[0];
    const int idx = sidx[0];

    float ls = 0.f;
#pragma unroll
    for (int k = 0; k < PER_TH; k++) {
        vals[k] = fast_exp(vals[k] - M);
        ls += vals[k];
    }
    ssum[tid] = ls;
    __syncthreads();
    for (int off = SM_THREADS / 2; off > 0; off >>= 1) {
        if (tid < off) ssum[tid] += ssum[tid + off];
        __syncthreads();
    }
    const float invZ = 1.0f / ssum[0];

#pragma unroll
    for (int k = 0; k < PER_TH; k++)
        P[tid + k * SM_THREADS] = vals[k] * invZ;

    if (tid == 0) out_index[b] = (float)idx;
    if (tid < FF)
        gathered[b * FF + tid] = enc_input[((size_t)b * SS + idx) * FF + tid];
}

// ---------------------------------------------------------------------------
// launch
// ---------------------------------------------------------------------------
extern "C" void kernel_launch(void* const* d_in, const int* in_sizes, int n_in,
                              void* d_out, int out_size) {
    const float* dec     = (const float*)d_in[0];
    const float* enc_in  = (const float*)d_in[1];
    const float* enc_out = (const float*)d_in[2];
    const float* mask    = (const float*)d_in[3];
    const float* W1w     = (const float*)d_in[4];
    const float* W1b     = (const float*)d_in[5];
    const float* W2w     = (const float*)d_in[6];
    const float* W2b     = (const float*)d_in[7];
    const float* Vw      = (const float*)d_in[8];
    const float* Vb      = (const float*)d_in[9];

    float* out    = (float*)d_out;
    float* logits = out;
    float* probs  = out + (size_t)BB * SS;
    float* oidx   = out + (size_t)2 * BB * SS;
    float* gath   = oidx + BB;

    cudaFuncSetAttribute(prep_kernel,
                         cudaFuncAttributeMaxDynamicSharedMemorySize, DD * UU * 4);
    cudaFuncSetAttribute(main_kernel,
                         cudaFuncAttributeMaxDynamicSharedMemorySize, SM_TOTAL);

    prep_kernel<<<BB + 16, 256, DD * UU * 4>>>(dec, W1w, W1b, W2b, W2w);
    main_kernel<<<GRID_MAIN, 256, SM_TOTAL>>>(enc_out, mask, Vw, Vb, logits);
    softmax_kernel<<<BB, SM_THREADS>>>(logits, enc_in, probs, oidx, gath);
}